// round 13
// baseline (speedup 1.0000x reference)
#include <cuda_runtime.h>
#include <cstdint>

// Problem: states [B=64, L=4096, D=256] f32; w [256] f32; bias scalar f32.
// out[b,l] = reverse_cumsum_l( dot(states[b,l,:], w) + bias )
//
// Single fused kernel, 1024 blocks x 256 threads, __launch_bounds__(256,7):
// all blocks co-resident (148*7=1036 >= 1024) at 56 warps/SM -- the
// streaming regime proven to hit 87% of HBM in R5.
//   Block (b, j) owns chunk (15-j) of batch b: rows [(15-j)*256, ...+256).
//   Phase 1: warp-per-row dot (__ldcs), values parked in smem only.
//   Phase 2: block suffix-scan; publish chunk total as one 64-bit
//            (flag|value) packet; poll the <=15 packets of LATER chunks
//            (= LOWER block indices -> backward deps, deadlock-free).
//   Replay reset: each block zeroes its own slot as its first instruction;
//   polls occur ~30us later. No fences/atomics in the streaming path.

static constexpr int B = 64;
static constexpr int L = 4096;
static constexpr int D = 256;               // 64 float4 per row
static constexpr int NB = 16;               // blocks per batch
static constexpr int CHUNK = L / NB;        // 256 rows per block
static constexpr int GRID = B * NB;         // 1024

__device__ unsigned long long g_slots[GRID];   // (flag<<32)|float_bits(total)

__global__ void __launch_bounds__(256, 7)
qvalue_fused(const float4* __restrict__ states4,
             const float4* __restrict__ w4,
             const float*  __restrict__ bias,
             float* __restrict__ out)
{
    __shared__ float vals[CHUNK];           // 1 KB
    __shared__ float warp_tot[8];
    __shared__ float warp_off[8];
    __shared__ float chunk_off_sh;

    const int bid  = blockIdx.x;
    const int b    = bid >> 4;
    const int j    = bid & 15;
    const int chunk = 15 - j;               // j=0 owns the LAST chunk
    const int t    = threadIdx.x;
    const int lane = t & 31;
    const int wid  = t >> 5;

    // replay reset: clear own slot before anything else
    if (t == 0)
        *((volatile unsigned long long*)&g_slots[bid]) = 0ULL;

    const float4 w0 = __ldg(&w4[lane]);
    const float4 w1 = __ldg(&w4[lane + 32]);
    const float  bv = __ldg(bias);

    const float4* slab = states4
        + ((size_t)b * L + (size_t)chunk * CHUNK) * (D / 4);

    // ---- phase 1: 32 rows per warp, 2 rows per iteration ----
    #pragma unroll 4
    for (int k = 0; k < CHUNK / 8; k += 2) {
        const int l0 = wid + k * 8;
        const int l1 = l0 + 8;
        const float4* r0 = slab + (size_t)l0 * (D / 4);
        const float4* r1 = slab + (size_t)l1 * (D / 4);

        float4 a0 = __ldcs(&r0[lane]);
        float4 a1 = __ldcs(&r0[lane + 32]);
        float4 c0 = __ldcs(&r1[lane]);
        float4 c1 = __ldcs(&r1[lane + 32]);

        float s0 = a0.x * w0.x + a0.y * w0.y + a0.z * w0.z + a0.w * w0.w
                 + a1.x * w1.x + a1.y * w1.y + a1.z * w1.z + a1.w * w1.w;
        float s1 = c0.x * w0.x + c0.y * w0.y + c0.z * w0.z + c0.w * w0.w
                 + c1.x * w1.x + c1.y * w1.y + c1.z * w1.z + c1.w * w1.w;

        #pragma unroll
        for (int off = 16; off > 0; off >>= 1) {
            s0 += __shfl_xor_sync(0xFFFFFFFFu, s0, off);
            s1 += __shfl_xor_sync(0xFFFFFFFFu, s1, off);
        }

        if (lane == 0) {
            vals[l0] = s0 + bv;
            vals[l1] = s1 + bv;
        }
    }
    __syncthreads();

    // ---- phase 2: block suffix scan + cross-chunk combine ----
    float v = vals[t];

    // inclusive SUFFIX scan within warp: lane i -> sum over lanes >= i
    float s = v;
    #pragma unroll
    for (int off = 1; off < 32; off <<= 1) {
        float n = __shfl_down_sync(0xFFFFFFFFu, s, off);
        if (lane < 32 - off) s += n;
    }

    if (lane == 0) warp_tot[wid] = s;       // warp full sum (lane 0's s)
    __syncthreads();

    // publish this chunk's total ASAP (thread 0)
    if (t == 0) {
        float tot = 0.f;
        #pragma unroll
        for (int w = 0; w < 8; w++) tot += warp_tot[w];
        unsigned long long pkt =
            (1ULL << 32) | (unsigned long long)__float_as_uint(tot);
        *((volatile unsigned long long*)&g_slots[bid]) = pkt;
    }

    // warp 0: suffix of warp totals (strictly after each warp)
    if (wid == 0) {
        float ws = (lane < 8) ? warp_tot[lane] : 0.f;
        float ss = ws;
        #pragma unroll
        for (int off = 1; off < 8; off <<= 1) {
            float n = __shfl_down_sync(0xFFFFFFFFu, ss, off);
            if (lane < 8 - off) ss += n;
        }
        if (lane < 8) warp_off[lane] = ss - ws;
    }

    // warp 1: poll the totals of LATER chunks (= lower block indices < j)
    if (wid == 1) {
        float p = 0.f;
        if (lane < j) {
            volatile unsigned long long* sp =
                (volatile unsigned long long*)&g_slots[(b << 4) | lane];
            unsigned long long x;
            do { x = *sp; } while ((x >> 32) == 0ULL);
            p = __uint_as_float((unsigned)(x & 0xFFFFFFFFULL));
        }
        __syncwarp();
        #pragma unroll
        for (int off = 16; off > 0; off >>= 1)
            p += __shfl_xor_sync(0xFFFFFFFFu, p, off);
        if (lane == 0) chunk_off_sh = p;
    }
    __syncthreads();

    // q = (sum of later chunks) + (warps after mine) + (suffix incl. me)
    out[(size_t)b * L + (size_t)chunk * CHUNK + t] =
        chunk_off_sh + warp_off[wid] + s;
}

extern "C" void kernel_launch(void* const* d_in, const int* in_sizes, int n_in,
                              void* d_out, int out_size)
{
    const float4* states4 = (const float4*)d_in[0];
    const float4* w4      = (const float4*)d_in[1];
    const float*  bias    = (const float*)d_in[2];
    float* out = (float*)d_out;

    qvalue_fused<<<GRID, 256>>>(states4, w4, bias, out);
}

// round 14
// speedup vs baseline: 1.0477x; 1.0477x over previous
#include <cuda_runtime.h>
#include <cstdint>

// Problem: states [B=64, L=4096, D=256] f32; w [256] f32; bias scalar f32.
// out[b,l] = reverse_cumsum_l( dot(states[b,l,:], w) + bias )
//
// Single fused kernel, TMA-pipelined streaming:
//   1024 blocks x 256 thr (16 chunks/batch, 256 rows each, contiguous 256KB).
//   Streaming via cp.async.bulk (no register dependency => MLP decoupled
//   from the consumer loop, fixing the 68-75% cap of register streaming):
//   3-deep x 8KB smem pipeline, L2::evict_first policy (= __ldcs).
//   Consumers: 8 warps dot 8 rows/tile from smem; values stay in smem.
//   Cross-chunk suffix combine: R13's proven 64-bit (flag|total) packet
//   publish/poll, backward deps only. occ=7 => all 1024 blocks co-resident.

static constexpr int B = 64;
static constexpr int L = 4096;
static constexpr int D = 256;
static constexpr int NB = 16;                 // chunks per batch
static constexpr int CHUNK = L / NB;          // 256 rows
static constexpr int GRID = B * NB;           // 1024
static constexpr int TILE_ROWS = 8;
static constexpr int TILE_BYTES = TILE_ROWS * D * 4;   // 8192
static constexpr int NTILES = CHUNK / TILE_ROWS;       // 32
static constexpr int NBUF = 3;

__device__ unsigned long long g_slots[GRID];  // (flag<<32)|float_bits(total)

__device__ __forceinline__ uint32_t smem_u32(const void* p) {
    uint32_t a;
    asm("{ .reg .u64 t; cvta.to.shared.u64 t, %1; cvt.u32.u64 %0, t; }"
        : "=r"(a) : "l"(p));
    return a;
}

__device__ __forceinline__ void mbar_init(uint32_t m, uint32_t cnt) {
    asm volatile("mbarrier.init.shared.b64 [%0], %1;" :: "r"(m), "r"(cnt) : "memory");
}
__device__ __forceinline__ void mbar_expect_tx(uint32_t m, uint32_t bytes) {
    asm volatile("mbarrier.arrive.expect_tx.shared.b64 _, [%0], %1;"
                 :: "r"(m), "r"(bytes) : "memory");
}
__device__ __forceinline__ void bulk_g2s(uint32_t dst, const void* src,
                                         uint32_t bytes, uint32_t m, uint64_t pol) {
    asm volatile(
        "cp.async.bulk.shared::cta.global.mbarrier::complete_tx::bytes.L2::cache_hint "
        "[%0], [%1], %2, [%3], %4;"
        :: "r"(dst), "l"(src), "r"(bytes), "r"(m), "l"(pol) : "memory");
}
__device__ __forceinline__ void mbar_wait(uint32_t m, uint32_t parity) {
    uint32_t done;
    asm volatile(
        "{\n\t.reg .pred p;\n\t"
        "mbarrier.try_wait.parity.acquire.cta.shared::cta.b64 p, [%1], %2;\n\t"
        "selp.b32 %0, 1, 0, p;\n\t}"
        : "=r"(done) : "r"(m), "r"(parity) : "memory");
    while (!done) {
        asm volatile(
            "{\n\t.reg .pred p;\n\t"
            "mbarrier.try_wait.parity.acquire.cta.shared::cta.b64 p, [%1], %2, 0x989680;\n\t"
            "selp.b32 %0, 1, 0, p;\n\t}"
            : "=r"(done) : "r"(m), "r"(parity) : "memory");
    }
}

__global__ void __launch_bounds__(256, 7)
qvalue_tma(const float* __restrict__ states,
           const float4* __restrict__ w4,
           const float*  __restrict__ bias,
           float* __restrict__ out)
{
    __shared__ __align__(16) float buf[NBUF][TILE_ROWS * D];  // 3 x 8KB
    __shared__ float vals[CHUNK];                             // 1KB
    __shared__ float warp_tot[8];
    __shared__ float warp_off[8];
    __shared__ float chunk_off_sh;
    __shared__ __align__(8) unsigned long long mbar[NBUF];

    const int bid   = blockIdx.x;
    const int b     = bid >> 4;
    const int j     = bid & 15;
    const int chunk = 15 - j;            // j=0 owns the LAST chunk
    const int t     = threadIdx.x;
    const int lane  = t & 31;
    const int wid   = t >> 5;

    if (t == 0) {
        // replay reset of own packet slot (polls happen ~35us later)
        *((volatile unsigned long long*)&g_slots[bid]) = 0ULL;
        #pragma unroll
        for (int i = 0; i < NBUF; i++)
            mbar_init(smem_u32(&mbar[i]), 1);
    }
    __syncthreads();

    const float* src = states + ((size_t)b * L + (size_t)chunk * CHUNK) * D;

    uint64_t pol;
    asm("createpolicy.fractional.L2::evict_first.b64 %0, 1.0;" : "=l"(pol));

    // prologue: fill all NBUF buffers
    if (t == 0) {
        #pragma unroll
        for (int p = 0; p < NBUF; p++) {
            uint32_t m = smem_u32(&mbar[p]);
            mbar_expect_tx(m, TILE_BYTES);
            bulk_g2s(smem_u32(&buf[p][0]), src + (size_t)p * TILE_ROWS * D,
                     TILE_BYTES, m, pol);
        }
    }

    const float4 w0 = __ldg(&w4[lane]);
    const float4 w1 = __ldg(&w4[lane + 32]);
    const float  bv = __ldg(bias);

    // ---- phase 1: TMA-fed tile loop ----
    for (int k = 0; k < NTILES; k++) {
        const int bi = k % NBUF;
        const uint32_t parity = (uint32_t)((k / NBUF) & 1);

        mbar_wait(smem_u32(&mbar[bi]), parity);

        // warp wid consumes tile row wid (256 floats)
        const float4* rb = reinterpret_cast<const float4*>(&buf[bi][wid * D]);
        float4 a0 = rb[lane];
        float4 a1 = rb[lane + 32];

        float s = a0.x * w0.x + a0.y * w0.y + a0.z * w0.z + a0.w * w0.w
                + a1.x * w1.x + a1.y * w1.y + a1.z * w1.z + a1.w * w1.w;

        #pragma unroll
        for (int off = 16; off > 0; off >>= 1)
            s += __shfl_xor_sync(0xFFFFFFFFu, s, off);

        if (lane == 0)
            vals[k * TILE_ROWS + wid] = s + bv;

        __syncthreads();   // all warps done with buf[bi]; vals write ordered

        if (t == 0 && k + NBUF < NTILES) {
            uint32_t m = smem_u32(&mbar[bi]);
            mbar_expect_tx(m, TILE_BYTES);
            bulk_g2s(smem_u32(&buf[bi][0]),
                     src + (size_t)(k + NBUF) * TILE_ROWS * D,
                     TILE_BYTES, m, pol);
        }
    }

    // ---- phase 2: block suffix scan + cross-chunk combine (R13-proven) ----
    float v = vals[t];

    // inclusive SUFFIX scan within warp: lane i -> sum over lanes >= i
    float s = v;
    #pragma unroll
    for (int off = 1; off < 32; off <<= 1) {
        float n = __shfl_down_sync(0xFFFFFFFFu, s, off);
        if (lane < 32 - off) s += n;
    }

    if (lane == 0) warp_tot[wid] = s;    // warp full sum
    __syncthreads();

    // publish this chunk's total ASAP (thread 0)
    if (t == 0) {
        float tot = 0.f;
        #pragma unroll
        for (int w = 0; w < 8; w++) tot += warp_tot[w];
        unsigned long long pkt =
            (1ULL << 32) | (unsigned long long)__float_as_uint(tot);
        *((volatile unsigned long long*)&g_slots[bid]) = pkt;
    }

    // warp 0: suffix of warp totals (strictly after each warp)
    if (wid == 0) {
        float ws = (lane < 8) ? warp_tot[lane] : 0.f;
        float ss = ws;
        #pragma unroll
        for (int off = 1; off < 8; off <<= 1) {
            float n = __shfl_down_sync(0xFFFFFFFFu, ss, off);
            if (lane < 8 - off) ss += n;
        }
        if (lane < 8) warp_off[lane] = ss - ws;
    }

    // warp 1: poll totals of LATER chunks (= lower block indices, co-resident)
    if (wid == 1) {
        float p = 0.f;
        if (lane < j) {
            volatile unsigned long long* sp =
                (volatile unsigned long long*)&g_slots[(b << 4) | lane];
            unsigned long long x;
            do { x = *sp; } while ((x >> 32) == 0ULL);
            p = __uint_as_float((unsigned)(x & 0xFFFFFFFFULL));
        }
        __syncwarp();
        #pragma unroll
        for (int off = 16; off > 0; off >>= 1)
            p += __shfl_xor_sync(0xFFFFFFFFu, p, off);
        if (lane == 0) chunk_off_sh = p;
    }
    __syncthreads();

    // q = (sum of later chunks) + (warps after mine) + (suffix incl. me)
    out[(size_t)b * L + (size_t)chunk * CHUNK + t] =
        chunk_off_sh + warp_off[wid] + s;
}

extern "C" void kernel_launch(void* const* d_in, const int* in_sizes, int n_in,
                              void* d_out, int out_size)
{
    const float*  states = (const float*)d_in[0];
    const float4* w4     = (const float4*)d_in[1];
    const float*  bias   = (const float*)d_in[2];
    float* out = (float*)d_out;

    qvalue_tma<<<GRID, 256>>>(states, w4, bias, out);
}